// round 14
// baseline (speedup 1.0000x reference)
#include <cuda_runtime.h>
#include <cuda_fp16.h>
#include <cstdint>

#define BN    128
#define NN    12000
#define NOMIC 3600
#define NFN   7000
#define FCC   56000
#define EE    57000
#define LL    4
#define LAT   100
#define KPAD  112
#define HPAD  120
#define EPSV  1e-5f
#define KSPL  360         // gemm1 k-splits
#define KCH   10          // k per split (360*10=3600)

// ---------------- scratch (device globals; no allocation allowed) ----------------
__device__ float  g_xT[NN * BN];          // x transposed [n][b]
__device__ float  g_xe[EE * BN];          // edge state [e][b] (in-place RMW)
__device__ __half g_zh[FCC * BN];         // z (pre-sigmoid) fp16
__device__ __half g_s [FCC * BN];         // s = sigmoid(LN(z))  fp16
__device__ __half g_hfc[FCC * BN];        // hfc fp16
__device__ __half g_W2h[KPAD * FCC];      // W2 fp16, padded k rows (>=100 are zero)
__device__ __half g_hh[BN * HPAD];        // elu(h) fp16, b-major, padded k (>=100 zero)
__device__ float  g_b3cum[LL * EE];       // cumulative b3 sums
__device__ float  g_hraw[LAT * BN];       // gemm1 accumulator [j][b]
__device__ float  g_red [2 * BN];         // LN sum/sumsq (raw)
__device__ int    g_fcount[NFN];          // edges per source function
__device__ int    g_foff[NFN];            // exclusive prefix of counts
__device__ int    g_fpos[NFN];            // fill cursors
__device__ int4   g_elist[NFN * 10];      // fs-sorted edge list (p, e, fs, 0); P<=NFN*8

// ---------------- helpers ----------------
__device__ __forceinline__ float4 ld_half4(const __half* p) {
    union { uint2 u; __half2 h[2]; } v;
    v.u = *reinterpret_cast<const uint2*>(p);
    float2 a = __half22float2(v.h[0]);
    float2 b = __half22float2(v.h[1]);
    return make_float4(a.x, a.y, b.x, b.y);
}
__device__ __forceinline__ void st_half4(__half* p, float4 v) {
    union { uint2 u; __half2 h[2]; } o;
    o.h[0] = __floats2half2_rn(v.x, v.y);
    o.h[1] = __floats2half2_rn(v.z, v.w);
    *reinterpret_cast<uint2*>(p) = o.u;
}
__device__ __forceinline__ float eluf(float v) { return v > 0.f ? v : expm1f(v); }
__device__ __forceinline__ unsigned packh(__half lo, __half hi) {
    __half2 h = __halves2half2(lo, hi);
    return *reinterpret_cast<unsigned*>(&h);
}

// ---------------- fused prep: zero out/hraw/red/counters + b3cum + W2->fp16 ----------------
__global__ void prepK(const float* __restrict__ b3, const float* __restrict__ W2,
                      float4* __restrict__ out, int n4) {
    int i = blockIdx.x * blockDim.x + threadIdx.x;
    if (i < n4) out[i] = make_float4(0.f, 0.f, 0.f, 0.f);
    if (i < LAT * BN) g_hraw[i] = 0.f;
    if (i < 2 * BN)   g_red[i] = 0.f;
    if (i < NFN)      { g_fcount[i] = 0; g_fpos[i] = 0; }
    if (i < EE) {
        float a = 0.f;
        #pragma unroll
        for (int l = 0; l < LL; l++) { a += b3[l * EE + i]; g_b3cum[l * EE + i] = a; }
    }
    if (i < (KPAD * FCC) / 4) {
        int k = (i * 4) / FCC;
        uint2 o;
        if (k < LAT) {
            float4 w = reinterpret_cast<const float4*>(W2)[i];
            __half2 h0 = __floats2half2_rn(w.x, w.y);
            __half2 h1 = __floats2half2_rn(w.z, w.w);
            o.x = *reinterpret_cast<unsigned*>(&h0);
            o.y = *reinterpret_cast<unsigned*>(&h1);
        } else {
            o.x = 0u; o.y = 0u;
        }
        reinterpret_cast<uint2*>(g_W2h)[i] = o;
    }
}

// ---------------- count edges per source function ----------------
__global__ void countK(const int* __restrict__ w3rows, int P) {
    int p = blockIdx.x * blockDim.x + threadIdx.x;
    if (p >= P) return;
    atomicAdd(&g_fcount[__ldg(&w3rows[p * 8]) >> 3], 1);
}

// ---------------- exclusive prefix scan over g_fcount (single block) ----------------
__global__ void scanK() {
    __shared__ int sdata[1024];
    __shared__ int carry;
    int t = threadIdx.x;
    if (t == 0) carry = 0;
    __syncthreads();
    for (int base = 0; base < NFN; base += 1024) {
        int v = (base + t < NFN) ? g_fcount[base + t] : 0;
        sdata[t] = v;
        __syncthreads();
        for (int off = 1; off < 1024; off <<= 1) {
            int x = (t >= off) ? sdata[t - off] : 0;
            __syncthreads();
            sdata[t] += x;
            __syncthreads();
        }
        if (base + t < NFN) g_foff[base + t] = carry + sdata[t] - v;
        __syncthreads();
        if (t == 1023) carry += sdata[1023];
        __syncthreads();
    }
}

// ---------------- fill fs-sorted edge list ----------------
__global__ void fillK(const int* __restrict__ w3rows, const int* __restrict__ w3cols, int P) {
    int p = blockIdx.x * blockDim.x + threadIdx.x;
    if (p >= P) return;
    int fs = __ldg(&w3rows[p * 8]) >> 3;
    int e  = __ldg(&w3cols[p * 8]);
    int pos = atomicAdd(&g_fpos[fs], 1);
    g_elist[g_foff[fs] + pos] = make_int4(p, e, fs, 0);
}

// ---------------- transpose x : [b][n] -> [n][b] ----------------
__global__ void transposeK(const float* __restrict__ x) {
    __shared__ float t[32][33];
    int n0 = blockIdx.x * 32, b0 = blockIdx.y * 32;
    for (int i = threadIdx.y; i < 32; i += 8)
        t[i][threadIdx.x] = x[(b0 + i) * NN + n0 + threadIdx.x];
    __syncthreads();
    for (int i = threadIdx.y; i < 32; i += 8)
        g_xT[(n0 + i) * BN + b0 + threadIdx.x] = t[threadIdx.x][i];
}

// ---------------- initial edge gather (float4, omic columns zeroed) ----------------
__global__ void gatherK(const int* __restrict__ src) {
    int i = blockIdx.x * blockDim.x + threadIdx.x;   // i = e*32 + lane
    if (i >= EE * 32) return;
    int e = i >> 5, lane = i & 31;
    int s = src[e];
    float4 v = make_float4(0.f, 0.f, 0.f, 0.f);
    if (s >= NOMIC)
        v = *reinterpret_cast<const float4*>(&g_xT[s * BN + lane * 4]);
    *reinterpret_cast<float4*>(&g_xe[e * BN + lane * 4]) = v;
}

// ---------------- gemm1: very fine split-K for occupancy ----------------
__global__ void gemm1K(const float* __restrict__ W1) {
    __shared__ float Wsm[KCH * 20];
    int jt = blockIdx.x, ks = blockIdx.y;   // 5 x KSPL
    int t = threadIdx.x;                    // 128
    for (int idx = t; idx < KCH * 20; idx += 128) {
        int k = idx / 20, j = idx % 20;
        Wsm[idx] = W1[(ks * KCH + k) * LAT + jt * 20 + j];
    }
    __syncthreads();
    float acc[20];
    #pragma unroll
    for (int j = 0; j < 20; j++) acc[j] = 0.f;
    int b = t;
    const float* xp = &g_xT[(ks * KCH) * BN + b];
    float xv[KCH];
    #pragma unroll
    for (int k = 0; k < KCH; k++) xv[k] = xp[k * BN];
    #pragma unroll
    for (int k = 0; k < KCH; k++) {
        #pragma unroll
        for (int j = 0; j < 20; j++) acc[j] += xv[k] * Wsm[k * 20 + j];
    }
    #pragma unroll
    for (int j = 0; j < 20; j++)
        atomicAdd(&g_hraw[(jt * 20 + j) * BN + b], acc[j]);
}

// elu(hraw + bias) -> g_hh [b][HPAD] fp16 (zero-padded k)
__global__ void gemm1finK(const float* __restrict__ b_ae1) {
    int i = blockIdx.x * blockDim.x + threadIdx.x;   // BN*HPAD
    if (i >= BN * HPAD) return;
    int b = i / HPAD, k = i % HPAD;
    float v = 0.f;
    if (k < LAT) v = eluf(g_hraw[k * BN + b] + b_ae1[k]);
    g_hh[i] = __float2half(v);
}

// ---------------- gemm2 via fp16 tensor cores: z = W2^T h + b2 ----------------
__global__ void __launch_bounds__(256) gemm2K(const float* __restrict__ b2) {
    __shared__ __half hh[BN * HPAD];        // 30720 B
    __shared__ float sSum[BN], sSq[BN];
    int t = threadIdx.x;
    {
        const uint4* s = reinterpret_cast<const uint4*>(g_hh);
        uint4* d = reinterpret_cast<uint4*>(hh);
        #pragma unroll
        for (int i = 0; i < 8; i++) {
            int idx = t + i * 256;
            if (idx < (BN * HPAD) / 8) d[idx] = s[idx];
        }
    }
    if (t < BN) { sSum[t] = 0.f; sSq[t] = 0.f; }
    __syncthreads();

    int w = t >> 5, lane = t & 31;
    int g = lane >> 2, tg = lane & 3;
    int jsub = w & 3, bhalf = w >> 2;
    int j0 = blockIdx.x * 64 + jsub * 16;
    int jr0 = j0 + g, jr1 = j0 + g + 8;

    float c[8][4];
    #pragma unroll
    for (int nt = 0; nt < 8; nt++)
        c[nt][0] = c[nt][1] = c[nt][2] = c[nt][3] = 0.f;

    #pragma unroll
    for (int ks = 0; ks < 7; ks++) {
        int k = ks * 16 + 2 * tg;
        unsigned a0 = packh(g_W2h[(size_t)k * FCC + jr0],       g_W2h[(size_t)(k + 1) * FCC + jr0]);
        unsigned a1 = packh(g_W2h[(size_t)k * FCC + jr1],       g_W2h[(size_t)(k + 1) * FCC + jr1]);
        unsigned a2 = packh(g_W2h[(size_t)(k + 8) * FCC + jr0], g_W2h[(size_t)(k + 9) * FCC + jr0]);
        unsigned a3 = packh(g_W2h[(size_t)(k + 8) * FCC + jr1], g_W2h[(size_t)(k + 9) * FCC + jr1]);
        #pragma unroll
        for (int nt = 0; nt < 8; nt++) {
            int nb = bhalf * 64 + nt * 8 + g;
            unsigned b0 = *reinterpret_cast<const unsigned*>(&hh[nb * HPAD + k]);
            unsigned b1 = *reinterpret_cast<const unsigned*>(&hh[nb * HPAD + k + 8]);
            asm volatile(
                "mma.sync.aligned.m16n8k16.row.col.f32.f16.f16.f32 "
                "{%0,%1,%2,%3}, {%4,%5,%6,%7}, {%8,%9}, {%0,%1,%2,%3};"
                : "+f"(c[nt][0]), "+f"(c[nt][1]), "+f"(c[nt][2]), "+f"(c[nt][3])
                : "r"(a0), "r"(a1), "r"(a2), "r"(a3), "r"(b0), "r"(b1));
        }
    }

    float bias0 = b2[jr0], bias1 = b2[jr1];
    #pragma unroll
    for (int nt = 0; nt < 8; nt++) {
        int bc = bhalf * 64 + nt * 8 + 2 * tg;
        float v0 = c[nt][0] + bias0, v1 = c[nt][1] + bias0;
        float v2 = c[nt][2] + bias1, v3 = c[nt][3] + bias1;
        *reinterpret_cast<__half2*>(&g_zh[(size_t)jr0 * BN + bc]) = __floats2half2_rn(v0, v1);
        *reinterpret_cast<__half2*>(&g_zh[(size_t)jr1 * BN + bc]) = __floats2half2_rn(v2, v3);
        atomicAdd(&sSum[bc],     v0 + v2);
        atomicAdd(&sSq[bc],      v0 * v0 + v2 * v2);
        atomicAdd(&sSum[bc + 1], v1 + v3);
        atomicAdd(&sSq[bc + 1],  v1 * v1 + v3 * v3);
    }
    __syncthreads();
    if (t < BN) {
        atomicAdd(&g_red[t], sSum[t]);
        atomicAdd(&g_red[BN + t], sSq[t]);
    }
}

// sigmoid(LN(z)) -> fp16 s; LN stats inline from raw sums
__global__ void sigK() {
    int i = blockIdx.x * blockDim.x + threadIdx.x;
    if (i >= FCC * 32) return;
    int lane = i & 31;
    const float inv = 1.f / (float)FCC;
    float4 z  = ld_half4(&g_zh[i * 4]);
    float4 sm = *reinterpret_cast<const float4*>(&g_red[lane * 4]);
    float4 sq = *reinterpret_cast<const float4*>(&g_red[BN + lane * 4]);
    float4 mu, rs;
    mu.x = sm.x * inv; mu.y = sm.y * inv; mu.z = sm.z * inv; mu.w = sm.w * inv;
    rs.x = rsqrtf(sq.x * inv - mu.x * mu.x + EPSV);
    rs.y = rsqrtf(sq.y * inv - mu.y * mu.y + EPSV);
    rs.z = rsqrtf(sq.z * inv - mu.z * mu.z + EPSV);
    rs.w = rsqrtf(sq.w * inv - mu.w * mu.w + EPSV);
    float4 v;
    v.x = 1.f / (1.f + __expf(-(z.x - mu.x) * rs.x));
    v.y = 1.f / (1.f + __expf(-(z.y - mu.y) * rs.y));
    v.z = 1.f / (1.f + __expf(-(z.z - mu.z) * rs.z));
    v.w = 1.f / (1.f + __expf(-(z.w - mu.w) * rs.w));
    st_half4(&g_s[i * 4], v);
}

// ---------------- spmm1 + groupLN + s*elu (warp per function, float4 over b) ----------------
__global__ void __launch_bounds__(256) spmm1K(const float* __restrict__ w1,
                                              const float* __restrict__ b1,
                                              int l) {
    __shared__ float ws[512];
    int t = threadIdx.x;            // 256
    int f0 = blockIdx.x * 8;
    ws[t]       = w1[f0 * 64 + t];
    ws[t + 256] = w1[f0 * 64 + 256 + t];
    __syncthreads();
    int w = t >> 5, lane = t & 31;
    int f = f0 + w;
    const float* wf = &ws[w * 64];
    float bc_l = 0.f;
    if (l > 0 && lane < 8) bc_l = __ldg(&g_b3cum[(l - 1) * EE + 8 * f + lane]);
    float4 a[8];
    #pragma unroll
    for (int c = 0; c < 8; c++) {
        float bv = __ldg(&b1[f * 8 + c]);
        a[c] = make_float4(bv, bv, bv, bv);
    }
    #pragma unroll
    for (int j = 0; j < 8; j++) {
        int e = 8 * f + j;
        float4 xv = *reinterpret_cast<const float4*>(&g_xe[e * BN + lane * 4]);
        float bc = __shfl_sync(0xffffffffu, bc_l, j);
        xv.x += bc; xv.y += bc; xv.z += bc; xv.w += bc;
        #pragma unroll
        for (int c = 0; c < 8; c++) {
            float wv = wf[j * 8 + c];
            a[c].x += xv.x * wv; a[c].y += xv.y * wv;
            a[c].z += xv.z * wv; a[c].w += xv.w * wv;
        }
    }
    float4 mu = make_float4(0.f, 0.f, 0.f, 0.f);
    #pragma unroll
    for (int c = 0; c < 8; c++) { mu.x += a[c].x; mu.y += a[c].y; mu.z += a[c].z; mu.w += a[c].w; }
    mu.x *= 0.125f; mu.y *= 0.125f; mu.z *= 0.125f; mu.w *= 0.125f;
    float4 var = make_float4(0.f, 0.f, 0.f, 0.f);
    #pragma unroll
    for (int c = 0; c < 8; c++) {
        float dx = a[c].x - mu.x, dy = a[c].y - mu.y, dz = a[c].z - mu.z, dw = a[c].w - mu.w;
        var.x += dx * dx; var.y += dy * dy; var.z += dz * dz; var.w += dw * dw;
    }
    float4 rs;
    rs.x = rsqrtf(var.x * 0.125f + EPSV);
    rs.y = rsqrtf(var.y * 0.125f + EPSV);
    rs.z = rsqrtf(var.z * 0.125f + EPSV);
    rs.w = rsqrtf(var.w * 0.125f + EPSV);
    #pragma unroll
    for (int c = 0; c < 8; c++) {
        int row = f * 8 + c;
        float4 sv = ld_half4(&g_s[row * BN + lane * 4]);
        float4 v;
        v.x = eluf((a[c].x - mu.x) * rs.x * sv.x);
        v.y = eluf((a[c].y - mu.y) * rs.y * sv.y);
        v.z = eluf((a[c].z - mu.z) * rs.z * sv.z);
        v.w = eluf((a[c].w - mu.w) * rs.w * sv.w);
        st_half4(&g_hfc[row * BN + lane * 4], v);
    }
}

// ---------------- spmm3 (warp per edge, fs-sorted order for L1 hfc reuse) ----------------
__global__ void __launch_bounds__(256) spmm3K(const float* __restrict__ w3, int P) {
    int idx = blockIdx.x * blockDim.x + threadIdx.x;
    int i = idx >> 5, lane = idx & 31;
    if (i >= P) return;
    int4 pe = g_elist[i];
    int p = pe.x, e = pe.y, fs = pe.z;
    float4 w0  = *reinterpret_cast<const float4*>(&w3[p * 8]);
    float4 w1v = *reinterpret_cast<const float4*>(&w3[p * 8 + 4]);
    float* xp = &g_xe[(size_t)e * BN + lane * 4];
    float4 acc = *reinterpret_cast<const float4*>(xp);
    const __half* hb = &g_hfc[(size_t)(fs * 8) * BN + lane * 4];
    float4 hv[8];
    #pragma unroll
    for (int c = 0; c < 8; c++) hv[c] = ld_half4(hb + (size_t)c * BN);
    acc.x += hv[0].x * w0.x + hv[1].x * w0.y + hv[2].x * w0.z + hv[3].x * w0.w
           + hv[4].x * w1v.x + hv[5].x * w1v.y + hv[6].x * w1v.z + hv[7].x * w1v.w;
    acc.y += hv[0].y * w0.x + hv[1].y * w0.y + hv[2].y * w0.z + hv[3].y * w0.w
           + hv[4].y * w1v.x + hv[5].y * w1v.y + hv[6].y * w1v.z + hv[7].y * w1v.w;
    acc.z += hv[0].z * w0.x + hv[1].z * w0.y + hv[2].z * w0.z + hv[3].z * w0.w
           + hv[4].z * w1v.x + hv[5].z * w1v.y + hv[6].z * w1v.z + hv[7].z * w1v.w;
    acc.w += hv[0].w * w0.x + hv[1].w * w0.y + hv[2].w * w0.z + hv[3].w * w0.w
           + hv[4].w * w1v.x + hv[5].w * w1v.y + hv[6].w * w1v.z + hv[7].w * w1v.w;
    *reinterpret_cast<float4*>(xp) = acc;
}

// ---------------- final: only out-edges survive the mask ----------------
__global__ void finalK(const int* __restrict__ dst, float* __restrict__ out) {
    int i = blockIdx.x * blockDim.x + threadIdx.x;   // 1000*128
    if (i >= 1000 * BN) return;
    int k = i >> 7, b = i & 127;
    int e = FCC + k;
    float v = (g_xe[(size_t)e * BN + b] + g_b3cum[3 * EE + e]) * 0.25f;
    out[b * NN + dst[e]] = v;
}

// ---------------- launch (single stream) ----------------
extern "C" void kernel_launch(void* const* d_in, const int* in_sizes, int n_in,
                              void* d_out, int out_size) {
    const float* x       = (const float*)d_in[0];
    const float* W_ae1   = (const float*)d_in[1];
    const float* b_ae1   = (const float*)d_in[2];
    const float* W_ae2   = (const float*)d_in[3];
    const float* b_ae2   = (const float*)d_in[4];
    const float* w1_vals = (const float*)d_in[5];
    const float* b1      = (const float*)d_in[6];
    const float* w3_vals = (const float*)d_in[7];
    const float* b3      = (const float*)d_in[8];
    const int*   src     = (const int*)  d_in[9];
    const int*   dst     = (const int*)  d_in[10];
    const int*   w3_rows = (const int*)  d_in[13];
    const int*   w3_cols = (const int*)  d_in[14];
    float* out = (float*)d_out;

    int nnz1 = in_sizes[5] / LL;
    int nnz3 = in_sizes[7] / LL;
    int P = nnz3 / 8;
    int n4 = out_size / 4;
    int prepN = (KPAD * FCC) / 4;
    if (prepN < n4) prepN = n4;
    if (prepN < EE) prepN = EE;

    prepK<<<(prepN + 255) / 256, 256>>>(b3, W_ae2, (float4*)out, n4);
    countK<<<(P + 255) / 256, 256>>>(w3_rows, P);
    scanK<<<1, 1024>>>();
    fillK<<<(P + 255) / 256, 256>>>(w3_rows, w3_cols, P);
    transposeK<<<dim3(NN / 32, BN / 32), dim3(32, 8)>>>(x);
    gatherK<<<(EE * 32 + 255) / 256, 256>>>(src);

    gemm1K<<<dim3(5, KSPL), 128>>>(W_ae1);
    gemm1finK<<<(BN * HPAD + 255) / 256, 256>>>(b_ae1);
    gemm2K<<<FCC / 64, 256>>>(b_ae2);
    sigK<<<(FCC * 32 + 255) / 256, 256>>>();

    for (int l = 0; l < LL; l++) {
        spmm1K<<<NFN / 8, 256>>>(w1_vals + (size_t)l * nnz1, b1 + (size_t)l * FCC, l);
        spmm3K<<<(P * 32 + 255) / 256, 256>>>(w3_vals + (size_t)l * nnz3, P);
    }

    finalK<<<(1000 * BN) / 256, 256>>>(dst, out);
}

// round 15
// speedup vs baseline: 1.1659x; 1.1659x over previous
#include <cuda_runtime.h>
#include <cuda_fp16.h>
#include <cstdint>

#define BN    128
#define NN    12000
#define NOMIC 3600
#define NFN   7000
#define FCC   56000
#define EE    57000
#define LL    4
#define LAT   100
#define NOUT  1000
#define KPAD  112
#define HPAD  120
#define EPSV  1e-5f
#define KSPL  240         // gemm1 k-splits
#define KCH   15          // k per split (240*15=3600)

// ---------------- scratch (device globals; no allocation allowed) ----------------
__device__ float  g_xT[NN * BN];          // x transposed [n][b]
__device__ float  g_xe[EE * BN];          // edge state [e][b] (in-place RMW)
__device__ __half g_zh[FCC * BN];         // z (pre-sigmoid) fp16
__device__ __half g_s [FCC * BN];         // s = sigmoid(LN(z))  fp16
__device__ __half g_hfc[FCC * BN];        // hfc fp16
__device__ __half g_W2h[KPAD * FCC];      // W2 fp16, padded k rows (>=100 are zero)
__device__ __half g_hh[BN * HPAD];        // elu(h) fp16, b-major, padded k (>=100 zero)
__device__ float  g_b3cum[LL * EE];       // cumulative b3 sums
__device__ float  g_hraw[LAT * BN];       // gemm1 accumulator [j][b]
__device__ float  g_red [2 * BN];         // LN sum/sumsq (raw)
__device__ int2   g_outlist[NOUT];        // (p, fs) for each out-edge e = FCC + k

// ---------------- helpers ----------------
__device__ __forceinline__ float4 ld_half4(const __half* p) {
    union { uint2 u; __half2 h[2]; } v;
    v.u = *reinterpret_cast<const uint2*>(p);
    float2 a = __half22float2(v.h[0]);
    float2 b = __half22float2(v.h[1]);
    return make_float4(a.x, a.y, b.x, b.y);
}
__device__ __forceinline__ void st_half4(__half* p, float4 v) {
    union { uint2 u; __half2 h[2]; } o;
    o.h[0] = __floats2half2_rn(v.x, v.y);
    o.h[1] = __floats2half2_rn(v.z, v.w);
    *reinterpret_cast<uint2*>(p) = o.u;
}
__device__ __forceinline__ float eluf(float v) { return v > 0.f ? v : expm1f(v); }
__device__ __forceinline__ unsigned packh(__half lo, __half hi) {
    __half2 h = __halves2half2(lo, hi);
    return *reinterpret_cast<unsigned*>(&h);
}

// ---------------- fused prep: zero out/hraw/red + b3cum + W2->fp16 + outlist ----------------
__global__ void prepK(const float* __restrict__ b3, const float* __restrict__ W2,
                      const int* __restrict__ w3rows, const int* __restrict__ w3cols,
                      int P, float4* __restrict__ out, int n4) {
    int i = blockIdx.x * blockDim.x + threadIdx.x;
    if (i < n4) out[i] = make_float4(0.f, 0.f, 0.f, 0.f);
    if (i < LAT * BN) g_hraw[i] = 0.f;
    if (i < 2 * BN)   g_red[i] = 0.f;
    if (i < EE) {
        float a = 0.f;
        #pragma unroll
        for (int l = 0; l < LL; l++) { a += b3[l * EE + i]; g_b3cum[l * EE + i] = a; }
    }
    if (i < P) {
        int e = __ldg(&w3cols[i * 8]);
        if (e >= FCC) {
            int fs = __ldg(&w3rows[i * 8]) >> 3;
            g_outlist[e - FCC] = make_int2(i, fs);   // unique slot, no atomics
        }
    }
    if (i < (KPAD * FCC) / 4) {
        int k = (i * 4) / FCC;
        uint2 o;
        if (k < LAT) {
            float4 w = reinterpret_cast<const float4*>(W2)[i];
            __half2 h0 = __floats2half2_rn(w.x, w.y);
            __half2 h1 = __floats2half2_rn(w.z, w.w);
            o.x = *reinterpret_cast<unsigned*>(&h0);
            o.y = *reinterpret_cast<unsigned*>(&h1);
        } else {
            o.x = 0u; o.y = 0u;
        }
        reinterpret_cast<uint2*>(g_W2h)[i] = o;
    }
}

// ---------------- transpose x : [b][n] -> [n][b] ----------------
__global__ void transposeK(const float* __restrict__ x) {
    __shared__ float t[32][33];
    int n0 = blockIdx.x * 32, b0 = blockIdx.y * 32;
    for (int i = threadIdx.y; i < 32; i += 8)
        t[i][threadIdx.x] = x[(b0 + i) * NN + n0 + threadIdx.x];
    __syncthreads();
    for (int i = threadIdx.y; i < 32; i += 8)
        g_xT[(n0 + i) * BN + b0 + threadIdx.x] = t[threadIdx.x][i];
}

// ---------------- initial edge gather (float4, omic columns zeroed) ----------------
__global__ void gatherK(const int* __restrict__ src) {
    int i = blockIdx.x * blockDim.x + threadIdx.x;   // i = e*32 + lane
    if (i >= EE * 32) return;
    int e = i >> 5, lane = i & 31;
    int s = src[e];
    float4 v = make_float4(0.f, 0.f, 0.f, 0.f);
    if (s >= NOMIC)
        v = *reinterpret_cast<const float4*>(&g_xT[s * BN + lane * 4]);
    *reinterpret_cast<float4*>(&g_xe[e * BN + lane * 4]) = v;
}

// ---------------- gemm1: very fine split-K for occupancy ----------------
__global__ void gemm1K(const float* __restrict__ W1) {
    __shared__ float Wsm[KCH * 20];
    int jt = blockIdx.x, ks = blockIdx.y;   // 5 x KSPL
    int t = threadIdx.x;                    // 128
    for (int idx = t; idx < KCH * 20; idx += 128) {
        int k = idx / 20, j = idx % 20;
        Wsm[idx] = W1[(ks * KCH + k) * LAT + jt * 20 + j];
    }
    __syncthreads();
    float acc[20];
    #pragma unroll
    for (int j = 0; j < 20; j++) acc[j] = 0.f;
    int b = t;
    const float* xp = &g_xT[(ks * KCH) * BN + b];
    float xv[KCH];
    #pragma unroll
    for (int k = 0; k < KCH; k++) xv[k] = xp[k * BN];
    #pragma unroll
    for (int k = 0; k < KCH; k++) {
        #pragma unroll
        for (int j = 0; j < 20; j++) acc[j] += xv[k] * Wsm[k * 20 + j];
    }
    #pragma unroll
    for (int j = 0; j < 20; j++)
        atomicAdd(&g_hraw[(jt * 20 + j) * BN + b], acc[j]);
}

// elu(hraw + bias) -> g_hh [b][HPAD] fp16 (zero-padded k)
__global__ void gemm1finK(const float* __restrict__ b_ae1) {
    int i = blockIdx.x * blockDim.x + threadIdx.x;   // BN*HPAD
    if (i >= BN * HPAD) return;
    int b = i / HPAD, k = i % HPAD;
    float v = 0.f;
    if (k < LAT) v = eluf(g_hraw[k * BN + b] + b_ae1[k]);
    g_hh[i] = __float2half(v);
}

// ---------------- gemm2 via fp16 tensor cores: z = W2^T h + b2 ----------------
__global__ void __launch_bounds__(256) gemm2K(const float* __restrict__ b2) {
    __shared__ __half hh[BN * HPAD];        // 30720 B
    __shared__ float sSum[BN], sSq[BN];
    int t = threadIdx.x;
    {
        const uint4* s = reinterpret_cast<const uint4*>(g_hh);
        uint4* d = reinterpret_cast<uint4*>(hh);
        #pragma unroll
        for (int i = 0; i < 8; i++) {
            int idx = t + i * 256;
            if (idx < (BN * HPAD) / 8) d[idx] = s[idx];
        }
    }
    if (t < BN) { sSum[t] = 0.f; sSq[t] = 0.f; }
    __syncthreads();

    int w = t >> 5, lane = t & 31;
    int g = lane >> 2, tg = lane & 3;
    int jsub = w & 3, bhalf = w >> 2;
    int j0 = blockIdx.x * 64 + jsub * 16;
    int jr0 = j0 + g, jr1 = j0 + g + 8;

    float c[8][4];
    #pragma unroll
    for (int nt = 0; nt < 8; nt++)
        c[nt][0] = c[nt][1] = c[nt][2] = c[nt][3] = 0.f;

    #pragma unroll
    for (int ks = 0; ks < 7; ks++) {
        int k = ks * 16 + 2 * tg;
        unsigned a0 = packh(g_W2h[(size_t)k * FCC + jr0],       g_W2h[(size_t)(k + 1) * FCC + jr0]);
        unsigned a1 = packh(g_W2h[(size_t)k * FCC + jr1],       g_W2h[(size_t)(k + 1) * FCC + jr1]);
        unsigned a2 = packh(g_W2h[(size_t)(k + 8) * FCC + jr0], g_W2h[(size_t)(k + 9) * FCC + jr0]);
        unsigned a3 = packh(g_W2h[(size_t)(k + 8) * FCC + jr1], g_W2h[(size_t)(k + 9) * FCC + jr1]);
        #pragma unroll
        for (int nt = 0; nt < 8; nt++) {
            int nb = bhalf * 64 + nt * 8 + g;
            unsigned b0 = *reinterpret_cast<const unsigned*>(&hh[nb * HPAD + k]);
            unsigned b1 = *reinterpret_cast<const unsigned*>(&hh[nb * HPAD + k + 8]);
            asm volatile(
                "mma.sync.aligned.m16n8k16.row.col.f32.f16.f16.f32 "
                "{%0,%1,%2,%3}, {%4,%5,%6,%7}, {%8,%9}, {%0,%1,%2,%3};"
                : "+f"(c[nt][0]), "+f"(c[nt][1]), "+f"(c[nt][2]), "+f"(c[nt][3])
                : "r"(a0), "r"(a1), "r"(a2), "r"(a3), "r"(b0), "r"(b1));
        }
    }

    float bias0 = b2[jr0], bias1 = b2[jr1];
    #pragma unroll
    for (int nt = 0; nt < 8; nt++) {
        int bc = bhalf * 64 + nt * 8 + 2 * tg;
        float v0 = c[nt][0] + bias0, v1 = c[nt][1] + bias0;
        float v2 = c[nt][2] + bias1, v3 = c[nt][3] + bias1;
        *reinterpret_cast<__half2*>(&g_zh[(size_t)jr0 * BN + bc]) = __floats2half2_rn(v0, v1);
        *reinterpret_cast<__half2*>(&g_zh[(size_t)jr1 * BN + bc]) = __floats2half2_rn(v2, v3);
        atomicAdd(&sSum[bc],     v0 + v2);
        atomicAdd(&sSq[bc],      v0 * v0 + v2 * v2);
        atomicAdd(&sSum[bc + 1], v1 + v3);
        atomicAdd(&sSq[bc + 1],  v1 * v1 + v3 * v3);
    }
    __syncthreads();
    if (t < BN) {
        atomicAdd(&g_red[t], sSum[t]);
        atomicAdd(&g_red[BN + t], sSq[t]);
    }
}

// sigmoid(LN(z)) -> fp16 s; LN stats inline from raw sums
__global__ void sigK() {
    int i = blockIdx.x * blockDim.x + threadIdx.x;
    if (i >= FCC * 32) return;
    int lane = i & 31;
    const float inv = 1.f / (float)FCC;
    float4 z  = ld_half4(&g_zh[i * 4]);
    float4 sm = *reinterpret_cast<const float4*>(&g_red[lane * 4]);
    float4 sq = *reinterpret_cast<const float4*>(&g_red[BN + lane * 4]);
    float4 mu, rs;
    mu.x = sm.x * inv; mu.y = sm.y * inv; mu.z = sm.z * inv; mu.w = sm.w * inv;
    rs.x = rsqrtf(sq.x * inv - mu.x * mu.x + EPSV);
    rs.y = rsqrtf(sq.y * inv - mu.y * mu.y + EPSV);
    rs.z = rsqrtf(sq.z * inv - mu.z * mu.z + EPSV);
    rs.w = rsqrtf(sq.w * inv - mu.w * mu.w + EPSV);
    float4 v;
    v.x = 1.f / (1.f + __expf(-(z.x - mu.x) * rs.x));
    v.y = 1.f / (1.f + __expf(-(z.y - mu.y) * rs.y));
    v.z = 1.f / (1.f + __expf(-(z.z - mu.z) * rs.z));
    v.w = 1.f / (1.f + __expf(-(z.w - mu.w) * rs.w));
    st_half4(&g_s[i * 4], v);
}

// ---------------- spmm1 + groupLN + s*elu (warp per function, float4 over b) ----------------
__global__ void __launch_bounds__(256) spmm1K(const float* __restrict__ w1,
                                              const float* __restrict__ b1,
                                              int l) {
    __shared__ float ws[512];
    int t = threadIdx.x;            // 256
    int f0 = blockIdx.x * 8;
    ws[t]       = w1[f0 * 64 + t];
    ws[t + 256] = w1[f0 * 64 + 256 + t];
    __syncthreads();
    int w = t >> 5, lane = t & 31;
    int f = f0 + w;
    const float* wf = &ws[w * 64];
    float bc_l = 0.f;
    if (l > 0 && lane < 8) bc_l = __ldg(&g_b3cum[(l - 1) * EE + 8 * f + lane]);
    float4 a[8];
    #pragma unroll
    for (int c = 0; c < 8; c++) {
        float bv = __ldg(&b1[f * 8 + c]);
        a[c] = make_float4(bv, bv, bv, bv);
    }
    #pragma unroll
    for (int j = 0; j < 8; j++) {
        int e = 8 * f + j;
        float4 xv = *reinterpret_cast<const float4*>(&g_xe[e * BN + lane * 4]);
        float bc = __shfl_sync(0xffffffffu, bc_l, j);
        xv.x += bc; xv.y += bc; xv.z += bc; xv.w += bc;
        #pragma unroll
        for (int c = 0; c < 8; c++) {
            float wv = wf[j * 8 + c];
            a[c].x += xv.x * wv; a[c].y += xv.y * wv;
            a[c].z += xv.z * wv; a[c].w += xv.w * wv;
        }
    }
    float4 mu = make_float4(0.f, 0.f, 0.f, 0.f);
    #pragma unroll
    for (int c = 0; c < 8; c++) { mu.x += a[c].x; mu.y += a[c].y; mu.z += a[c].z; mu.w += a[c].w; }
    mu.x *= 0.125f; mu.y *= 0.125f; mu.z *= 0.125f; mu.w *= 0.125f;
    float4 var = make_float4(0.f, 0.f, 0.f, 0.f);
    #pragma unroll
    for (int c = 0; c < 8; c++) {
        float dx = a[c].x - mu.x, dy = a[c].y - mu.y, dz = a[c].z - mu.z, dw = a[c].w - mu.w;
        var.x += dx * dx; var.y += dy * dy; var.z += dz * dz; var.w += dw * dw;
    }
    float4 rs;
    rs.x = rsqrtf(var.x * 0.125f + EPSV);
    rs.y = rsqrtf(var.y * 0.125f + EPSV);
    rs.z = rsqrtf(var.z * 0.125f + EPSV);
    rs.w = rsqrtf(var.w * 0.125f + EPSV);
    #pragma unroll
    for (int c = 0; c < 8; c++) {
        int row = f * 8 + c;
        float4 sv = ld_half4(&g_s[row * BN + lane * 4]);
        float4 v;
        v.x = eluf((a[c].x - mu.x) * rs.x * sv.x);
        v.y = eluf((a[c].y - mu.y) * rs.y * sv.y);
        v.z = eluf((a[c].z - mu.z) * rs.z * sv.z);
        v.w = eluf((a[c].w - mu.w) * rs.w * sv.w);
        st_half4(&g_hfc[row * BN + lane * 4], v);
    }
}

// ---------------- spmm3 (warp per fe-edge, fully parallel, float4 xe RMW) ----------------
__global__ void __launch_bounds__(256) spmm3K(const float* __restrict__ w3,
                                              const int* __restrict__ w3rows,
                                              const int* __restrict__ w3cols,
                                              int P) {
    int idx = blockIdx.x * blockDim.x + threadIdx.x;
    int p = idx >> 5, lane = idx & 31;
    if (p >= P) return;
    int fs = __ldg(&w3rows[p * 8]) >> 3;
    int e  = __ldg(&w3cols[p * 8]);
    float4 w0  = *reinterpret_cast<const float4*>(&w3[p * 8]);
    float4 w1v = *reinterpret_cast<const float4*>(&w3[p * 8 + 4]);
    float* xp = &g_xe[(size_t)e * BN + lane * 4];
    float4 acc = *reinterpret_cast<const float4*>(xp);
    const __half* hb = &g_hfc[(size_t)(fs * 8) * BN + lane * 4];
    float4 hv[8];
    #pragma unroll
    for (int c = 0; c < 8; c++) hv[c] = ld_half4(hb + (size_t)c * BN);
    acc.x += hv[0].x * w0.x + hv[1].x * w0.y + hv[2].x * w0.z + hv[3].x * w0.w
           + hv[4].x * w1v.x + hv[5].x * w1v.y + hv[6].x * w1v.z + hv[7].x * w1v.w;
    acc.y += hv[0].y * w0.x + hv[1].y * w0.y + hv[2].y * w0.z + hv[3].y * w0.w
           + hv[4].y * w1v.x + hv[5].y * w1v.y + hv[6].y * w1v.z + hv[7].y * w1v.w;
    acc.z += hv[0].z * w0.x + hv[1].z * w0.y + hv[2].z * w0.z + hv[3].z * w0.w
           + hv[4].z * w1v.x + hv[5].z * w1v.y + hv[6].z * w1v.z + hv[7].z * w1v.w;
    acc.w += hv[0].w * w0.x + hv[1].w * w0.y + hv[2].w * w0.z + hv[3].w * w0.w
           + hv[4].w * w1v.x + hv[5].w * w1v.y + hv[6].w * w1v.z + hv[7].w * w1v.w;
    *reinterpret_cast<float4*>(xp) = acc;
}

// ---------------- layer 3 fused: only out-edge destinations matter ----------------
// Warp per out-edge k: recompute source function's hfc in registers, apply w3 dot,
// update xe[FCC+k]. Identical math to spmm1(l=3)+spmm3(l=3) for these edges.
__global__ void __launch_bounds__(256) layer3K(const float* __restrict__ w1,
                                               const float* __restrict__ b1,
                                               const float* __restrict__ w3) {
    int idx = blockIdx.x * blockDim.x + threadIdx.x;
    int k = idx >> 5, lane = idx & 31;
    if (k >= NOUT) return;
    int2 pf = g_outlist[k];
    int p = pf.x, fs = pf.y;
    const float* wf = &w1[fs * 64];
    float bc_l = 0.f;
    if (lane < 8) bc_l = __ldg(&g_b3cum[2 * EE + 8 * fs + lane]);   // l=3 -> cum[l-1=2]
    float4 a[8];
    #pragma unroll
    for (int c = 0; c < 8; c++) {
        float bv = __ldg(&b1[fs * 8 + c]);
        a[c] = make_float4(bv, bv, bv, bv);
    }
    #pragma unroll
    for (int j = 0; j < 8; j++) {
        int e2 = 8 * fs + j;
        float4 xv = *reinterpret_cast<const float4*>(&g_xe[(size_t)e2 * BN + lane * 4]);
        float bc = __shfl_sync(0xffffffffu, bc_l, j);
        xv.x += bc; xv.y += bc; xv.z += bc; xv.w += bc;
        #pragma unroll
        for (int c = 0; c < 8; c++) {
            float wv = __ldg(&wf[j * 8 + c]);
            a[c].x += xv.x * wv; a[c].y += xv.y * wv;
            a[c].z += xv.z * wv; a[c].w += xv.w * wv;
        }
    }
    float4 mu = make_float4(0.f, 0.f, 0.f, 0.f);
    #pragma unroll
    for (int c = 0; c < 8; c++) { mu.x += a[c].x; mu.y += a[c].y; mu.z += a[c].z; mu.w += a[c].w; }
    mu.x *= 0.125f; mu.y *= 0.125f; mu.z *= 0.125f; mu.w *= 0.125f;
    float4 var = make_float4(0.f, 0.f, 0.f, 0.f);
    #pragma unroll
    for (int c = 0; c < 8; c++) {
        float dx = a[c].x - mu.x, dy = a[c].y - mu.y, dz = a[c].z - mu.z, dw = a[c].w - mu.w;
        var.x += dx * dx; var.y += dy * dy; var.z += dz * dz; var.w += dw * dw;
    }
    float4 rs;
    rs.x = rsqrtf(var.x * 0.125f + EPSV);
    rs.y = rsqrtf(var.y * 0.125f + EPSV);
    rs.z = rsqrtf(var.z * 0.125f + EPSV);
    rs.w = rsqrtf(var.w * 0.125f + EPSV);
    #pragma unroll
    for (int c = 0; c < 8; c++) {
        int row = fs * 8 + c;
        float4 sv = ld_half4(&g_s[(size_t)row * BN + lane * 4]);
        a[c].x = eluf((a[c].x - mu.x) * rs.x * sv.x);
        a[c].y = eluf((a[c].y - mu.y) * rs.y * sv.y);
        a[c].z = eluf((a[c].z - mu.z) * rs.z * sv.z);
        a[c].w = eluf((a[c].w - mu.w) * rs.w * sv.w);
    }
    float4 w0  = *reinterpret_cast<const float4*>(&w3[p * 8]);
    float4 w1v = *reinterpret_cast<const float4*>(&w3[p * 8 + 4]);
    float* xp = &g_xe[(size_t)(FCC + k) * BN + lane * 4];
    float4 acc = *reinterpret_cast<const float4*>(xp);
    acc.x += a[0].x * w0.x + a[1].x * w0.y + a[2].x * w0.z + a[3].x * w0.w
           + a[4].x * w1v.x + a[5].x * w1v.y + a[6].x * w1v.z + a[7].x * w1v.w;
    acc.y += a[0].y * w0.x + a[1].y * w0.y + a[2].y * w0.z + a[3].y * w0.w
           + a[4].y * w1v.x + a[5].y * w1v.y + a[6].y * w1v.z + a[7].y * w1v.w;
    acc.z += a[0].z * w0.x + a[1].z * w0.y + a[2].z * w0.z + a[3].z * w0.w
           + a[4].z * w1v.x + a[5].z * w1v.y + a[6].z * w1v.z + a[7].z * w1v.w;
    acc.w += a[0].w * w0.x + a[1].w * w0.y + a[2].w * w0.z + a[3].w * w0.w
           + a[4].w * w1v.x + a[5].w * w1v.y + a[6].w * w1v.z + a[7].w * w1v.w;
    *reinterpret_cast<float4*>(xp) = acc;
}

// ---------------- final: only out-edges survive the mask ----------------
__global__ void finalK(const int* __restrict__ dst, float* __restrict__ out) {
    int i = blockIdx.x * blockDim.x + threadIdx.x;   // 1000*128
    if (i >= NOUT * BN) return;
    int k = i >> 7, b = i & 127;
    int e = FCC + k;
    float v = (g_xe[(size_t)e * BN + b] + g_b3cum[3 * EE + e]) * 0.25f;
    out[b * NN + dst[e]] = v;
}

// ---------------- launch (single stream) ----------------
extern "C" void kernel_launch(void* const* d_in, const int* in_sizes, int n_in,
                              void* d_out, int out_size) {
    const float* x       = (const float*)d_in[0];
    const float* W_ae1   = (const float*)d_in[1];
    const float* b_ae1   = (const float*)d_in[2];
    const float* W_ae2   = (const float*)d_in[3];
    const float* b_ae2   = (const float*)d_in[4];
    const float* w1_vals = (const float*)d_in[5];
    const float* b1      = (const float*)d_in[6];
    const float* w3_vals = (const float*)d_in[7];
    const float* b3      = (const float*)d_in[8];
    const int*   src     = (const int*)  d_in[9];
    const int*   dst     = (const int*)  d_in[10];
    const int*   w3_rows = (const int*)  d_in[13];
    const int*   w3_cols = (const int*)  d_in[14];
    float* out = (float*)d_out;

    int nnz1 = in_sizes[5] / LL;
    int nnz3 = in_sizes[7] / LL;
    int P = nnz3 / 8;
    int n4 = out_size / 4;
    int prepN = (KPAD * FCC) / 4;
    if (prepN < n4) prepN = n4;
    if (prepN < EE) prepN = EE;
    if (prepN < P)  prepN = P;

    prepK<<<(prepN + 255) / 256, 256>>>(b3, W_ae2, w3_rows, w3_cols, P, (float4*)out, n4);
    transposeK<<<dim3(NN / 32, BN / 32), dim3(32, 8)>>>(x);
    gatherK<<<(EE * 32 + 255) / 256, 256>>>(src);

    gemm1K<<<dim3(5, KSPL), 128>>>(W_ae1);
    gemm1finK<<<(BN * HPAD + 255) / 256, 256>>>(b_ae1);
    gemm2K<<<FCC / 64, 256>>>(b_ae2);
    sigK<<<(FCC * 32 + 255) / 256, 256>>>();

    for (int l = 0; l < LL - 1; l++) {
        spmm1K<<<NFN / 8, 256>>>(w1_vals + (size_t)l * nnz1, b1 + (size_t)l * FCC, l);
        spmm3K<<<(P * 32 + 255) / 256, 256>>>(w3_vals + (size_t)l * nnz3, w3_rows, w3_cols, P);
    }
    layer3K<<<(NOUT * 32 + 255) / 256, 256>>>(w1_vals + (size_t)3 * nnz1,
                                              b1 + (size_t)3 * FCC,
                                              w3_vals + (size_t)3 * nnz3);

    finalK<<<(NOUT * BN + 255) / 256, 256>>>(dst, out);
}